// round 5
// baseline (speedup 1.0000x reference)
#include <cuda_runtime.h>
#include <math.h>

#define NROI 116
#define NGR  128
#define HID  64
#define EDIM 5
#define INCH 116
#define EMBD 16
#define CIN  (INCH + EMBD)
#define EPG  (NROI * NROI)
#define NNODE (NROI * NGR)
#define RS   68
#define THR  928

__device__ float g_hpre[NNODE * HID];
__device__ float g_hA[NNODE * HID];
__device__ float g_hB[NNODE * HID];
__device__ float g_sum[HID];
__device__ float g_sumsq[HID];
__device__ float g_scale[HID];
__device__ float g_shift[HID];
__device__ float g_t[NNODE];
__device__ float g_MS[2];
// transposed edge attrs: [g][d][s][8] (5 attrs + 3 pad), 16B aligned rows
__device__ float g_eaT2[(size_t)NGR * NROI * NROI * 8];

__device__ __forceinline__ float4 ld4(const float* p) { return *reinterpret_cast<const float4*>(p); }
__device__ __forceinline__ void st4(float* p, float4 v) { *reinterpret_cast<float4*>(p) = v; }
__device__ __forceinline__ float4 fma4(float a, float4 b, float4 c) {
    c.x = fmaf(a, b.x, c.x); c.y = fmaf(a, b.y, c.y);
    c.z = fmaf(a, b.z, c.z); c.w = fmaf(a, b.w, c.w); return c;
}
__device__ __forceinline__ float4 add4(float4 a, float4 b) {
    a.x += b.x; a.y += b.y; a.z += b.z; a.w += b.w; return a;
}
__device__ __forceinline__ float4 relu4(float4 a) {
    a.x = fmaxf(a.x, 0.f); a.y = fmaxf(a.y, 0.f);
    a.z = fmaxf(a.z, 0.f); a.w = fmaxf(a.w, 0.f); return a;
}
__device__ __forceinline__ float4 scale4(float4 a, float f) {
    a.x *= f; a.y *= f; a.z *= f; a.w *= f; return a;
}
__device__ __forceinline__ float4 leaky4(float4 u) {
    float4 r;
    r.x = fmaxf(u.x, 0.f) + 0.2f * fminf(u.x, 0.f);
    r.y = fmaxf(u.y, 0.f) + 0.2f * fminf(u.y, 0.f);
    r.z = fmaxf(u.z, 0.f) + 0.2f * fminf(u.z, 0.f);
    r.w = fmaxf(u.w, 0.f) + 0.2f * fminf(u.w, 0.f);
    return r;
}
__device__ __forceinline__ float4 zero4() { return make_float4(0.f, 0.f, 0.f, 0.f); }

__global__ void k_init() {
    int t = threadIdx.x;
    if (t < HID) { g_sum[t] = 0.f; g_sumsq[t] = 0.f; }
}

// transpose edge attrs into [g][d][s][8]; writes coalesced (32B/thread, s-major)
__global__ void __launch_bounds__(256) k_etrans(const float* __restrict__ ea) {
    long long t = (long long)blockIdx.x * 256 + threadIdx.x;
    if (t >= (long long)NGR * EPG) return;
    int g = (int)(t / EPG);
    int r = (int)(t - (long long)g * EPG);
    int d = r / NROI;
    int s = r - d * NROI;
    const float* src = ea + ((size_t)g * EPG + (size_t)s * NROI + d) * EDIM;
    float4 a = make_float4(__ldg(src), __ldg(src + 1), __ldg(src + 2), __ldg(src + 3));
    float4 b = make_float4(__ldg(src + 4), 0.f, 0.f, 0.f);
    float* dst = g_eaT2 + (((size_t)g * NROI + d) * NROI + s) * 8;
    st4(dst, a); st4(dst + 4, b);
}

__global__ void __launch_bounds__(THR) k_encode(
    const float* __restrict__ x, const float* __restrict__ emb,
    const int* __restrict__ gid,
    const float* __restrict__ W, const float* __restrict__ b)
{
    extern __shared__ float sm[];
    float* XC = sm;
    float* WE = XC + NROI * CIN;
    float* HS = WE + CIN * HID;
    float* BS = HS + NROI * RS;
    int g = blockIdx.x, tid = threadIdx.x;

    for (int i = tid; i < CIN * HID; i += THR) WE[i] = W[i];
    if (tid < HID) BS[tid] = b[tid];
    const float* xg = x + (size_t)g * NROI * INCH;
    for (int i = tid; i < NROI * INCH; i += THR) {
        int n = i / INCH, c = i - n * INCH;
        XC[n * CIN + c] = xg[i];
    }
    for (int i = tid; i < NROI * EMBD; i += THR) {
        int n = i / EMBD, k = i - n * EMBD;
        XC[n * CIN + INCH + k] = emb[gid[g * NROI + n] * EMBD + k];
    }
    __syncthreads();

    int n = tid >> 3, jg = tid & 7, j0 = jg * 8;
    {
        float4 a0 = ld4(BS + j0), a1 = ld4(BS + j0 + 4);
        const float* xr = XC + n * CIN;
        #pragma unroll 4
        for (int c = 0; c < CIN; c++) {
            float xv = xr[c];
            const float* wr = WE + c * HID + j0;
            a0 = fma4(xv, ld4(wr), a0);
            a1 = fma4(xv, ld4(wr + 4), a1);
        }
        a0 = relu4(a0); a1 = relu4(a1);
        float* hp = g_hpre + ((size_t)g * NROI + n) * HID + j0;
        float* hs = HS + n * RS + j0;
        st4(hp, a0); st4(hp + 4, a1);
        st4(hs, a0); st4(hs + 4, a1);
    }
    __syncthreads();

    if (tid < HID) {
        float s1 = 0.f, s2 = 0.f;
        for (int r = 0; r < NROI; r++) {
            float v = HS[r * RS + tid];
            s1 += v; s2 += v * v;
        }
        atomicAdd(&g_sum[tid], s1);
        atomicAdd(&g_sumsq[tid], s2);
    }
}

__global__ void k_bnfin(const float* __restrict__ gg, const float* __restrict__ gb) {
    int j = threadIdx.x;
    if (j < HID) {
        const float invN = 1.0f / (float)NNODE;
        float mu  = g_sum[j] * invN;
        float var = g_sumsq[j] * invN - mu * mu;
        float sc  = gg[j] * rsqrtf(var + 1e-5f);
        g_scale[j] = sc;
        g_shift[j] = gb[j] - mu * sc;
    }
}

__global__ void __launch_bounds__(THR) k_gine(
    const float* __restrict__ We, const float* __restrict__ be,
    const float* __restrict__ W1, const float* __restrict__ b1,
    const float* __restrict__ W2, const float* __restrict__ b2)
{
    extern __shared__ float sm[];
    float* H   = sm;
    float* AG  = H + NROI * RS;
    float* W1s = AG + NROI * RS;
    float* W2s = W1s + HID * HID;
    float* WEs = W2s + HID * HID;
    float* BEs = WEs + EDIM * HID;
    float* B1s = BEs + HID;
    float* B2s = B1s + HID;
    int g = blockIdx.x, tid = threadIdx.x;

    for (int i = tid; i < HID * HID; i += THR) { W1s[i] = W1[i]; W2s[i] = W2[i]; }
    if (tid < EDIM * HID) WEs[tid] = We[tid];
    if (tid < HID) { BEs[tid] = be[tid]; B1s[tid] = b1[tid]; B2s[tid] = b2[tid]; }
    const float* hp = g_hpre + (size_t)g * NROI * HID;
    for (int i = tid; i < NROI * HID; i += THR) {
        int n = i >> 6, j = i & 63;
        H[n * RS + j] = hp[i] * g_scale[j] + g_shift[j];
    }
    __syncthreads();

    int d = tid >> 3, jg = tid & 7, j0 = jg * 8;

    {
        float4 w00 = ld4(WEs + 0 * HID + j0), w01 = ld4(WEs + 0 * HID + j0 + 4);
        float4 w10 = ld4(WEs + 1 * HID + j0), w11 = ld4(WEs + 1 * HID + j0 + 4);
        float4 w20 = ld4(WEs + 2 * HID + j0), w21 = ld4(WEs + 2 * HID + j0 + 4);
        float4 w30 = ld4(WEs + 3 * HID + j0), w31 = ld4(WEs + 3 * HID + j0 + 4);
        float4 w40 = ld4(WEs + 4 * HID + j0), w41 = ld4(WEs + 4 * HID + j0 + 4);
        float4 acc0 = zero4(), acc1 = zero4();
        const float* ep = g_eaT2 + ((size_t)g * NROI + d) * NROI * 8;
        const float* Hj = H + j0;
        const float* BEj = BEs + j0;

        #pragma unroll 4
        for (int s = 0; s < NROI; s++) {
            float4 E = ld4(ep + s * 8);
            float e4 = __ldg(ep + s * 8 + 4);
            float4 p0 = ld4(BEj), p1 = ld4(BEj + 4);
            p0 = fma4(E.x, w00, p0);  p1 = fma4(E.x, w01, p1);
            p0 = fma4(E.y, w10, p0);  p1 = fma4(E.y, w11, p1);
            p0 = fma4(E.z, w20, p0);  p1 = fma4(E.z, w21, p1);
            p0 = fma4(E.w, w30, p0);  p1 = fma4(E.w, w31, p1);
            p0 = fma4(e4,  w40, p0);  p1 = fma4(e4,  w41, p1);
            const float* hr = Hj + s * RS;
            acc0 = add4(acc0, relu4(add4(ld4(hr), p0)));
            acc1 = add4(acc1, relu4(add4(ld4(hr + 4), p1)));
        }
        float* agr = AG + d * RS + j0;
        const float* hd = Hj + d * RS;
        st4(agr,     add4(acc0, ld4(hd)));
        st4(agr + 4, add4(acc1, ld4(hd + 4)));
    }
    __syncthreads();

    {
        float4 a0 = ld4(B1s + j0), a1 = ld4(B1s + j0 + 4);
        const float* inr = AG + d * RS;
        #pragma unroll 4
        for (int c = 0; c < HID; c++) {
            float xv = inr[c];
            const float* wr = W1s + c * HID + j0;
            a0 = fma4(xv, ld4(wr), a0);
            a1 = fma4(xv, ld4(wr + 4), a1);
        }
        float* hr = H + d * RS + j0;
        st4(hr, relu4(a0)); st4(hr + 4, relu4(a1));
    }
    __syncthreads();

    {
        float4 a0 = ld4(B2s + j0), a1 = ld4(B2s + j0 + 4);
        const float* inr = H + d * RS;
        #pragma unroll 4
        for (int c = 0; c < HID; c++) {
            float xv = inr[c];
            const float* wr = W2s + c * HID + j0;
            a0 = fma4(xv, ld4(wr), a0);
            a1 = fma4(xv, ld4(wr + 4), a1);
        }
        float* og = g_hA + ((size_t)g * NROI + d) * HID + j0;
        st4(og, relu4(a0)); st4(og + 4, relu4(a1));
    }
}

__global__ void __launch_bounds__(THR) k_gat(
    int layer,
    const float* __restrict__ Wl_all, const float* __restrict__ bl_all,
    const float* __restrict__ Wr_all, const float* __restrict__ br_all,
    const float* __restrict__ att_all, const float* __restrict__ We_all,
    const float* __restrict__ bias_all)
{
    const float* in  = (layer == 0) ? g_hA : g_hB;
    float*       op  = (layer == 0) ? g_hB : g_hA;
    const float* Wl  = Wl_all  + layer * HID * HID;
    const float* bl  = bl_all  + layer * HID;
    const float* Wr  = Wr_all  + layer * HID * HID;
    const float* br  = br_all  + layer * HID;
    const float* att = att_all + layer * HID;
    const float* Wee = We_all  + layer * EDIM * HID;
    const float* bia = bias_all + layer * HID;

    extern __shared__ float sm[];
    float* H   = sm;
    float* XL  = H + NROI * RS;
    float* XR  = XL + NROI * RS;
    float* Ws  = XR + NROI * RS;
    float* WEs = Ws + HID * HID;
    float* ATT = WEs + EDIM * HID;
    float* BV  = ATT + HID;
    float* BI  = BV + HID;
    int g = blockIdx.x, tid = threadIdx.x;

    const float* ing = in + (size_t)g * NROI * HID;
    for (int i = tid; i < NROI * HID; i += THR)
        H[(i >> 6) * RS + (i & 63)] = ing[i];
    for (int i = tid; i < HID * HID; i += THR) Ws[i] = Wl[i];
    if (tid < EDIM * HID) WEs[tid] = Wee[tid];
    if (tid < HID) { ATT[tid] = att[tid]; BV[tid] = bl[tid]; BI[tid] = bia[tid]; }
    __syncthreads();

    int n = tid >> 3, jg = tid & 7, j0 = jg * 8;

    {
        float4 a0 = ld4(BV + j0), a1 = ld4(BV + j0 + 4);
        const float* hr = H + n * RS;
        #pragma unroll 4
        for (int c = 0; c < HID; c++) {
            float xv = hr[c];
            const float* wr = Ws + c * HID + j0;
            a0 = fma4(xv, ld4(wr), a0);
            a1 = fma4(xv, ld4(wr + 4), a1);
        }
        float* o = XL + n * RS + j0;
        st4(o, a0); st4(o + 4, a1);
    }
    __syncthreads();
    for (int i = tid; i < HID * HID; i += THR) Ws[i] = Wr[i];
    if (tid < HID) BV[tid] = br[tid];
    __syncthreads();
    {
        float4 a0 = ld4(BV + j0), a1 = ld4(BV + j0 + 4);
        const float* hr = H + n * RS;
        #pragma unroll 4
        for (int c = 0; c < HID; c++) {
            float xv = hr[c];
            const float* wr = Ws + c * HID + j0;
            a0 = fma4(xv, ld4(wr), a0);
            a1 = fma4(xv, ld4(wr + 4), a1);
        }
        float* o = XR + n * RS + j0;
        st4(o, a0); st4(o + 4, a1);
    }
    __syncthreads();

    {
        float4 w00 = ld4(WEs + 0 * HID + j0), w01 = ld4(WEs + 0 * HID + j0 + 4);
        float4 w10 = ld4(WEs + 1 * HID + j0), w11 = ld4(WEs + 1 * HID + j0 + 4);
        float4 w20 = ld4(WEs + 2 * HID + j0), w21 = ld4(WEs + 2 * HID + j0 + 4);
        float4 w30 = ld4(WEs + 3 * HID + j0), w31 = ld4(WEs + 3 * HID + j0 + 4);
        float4 w40 = ld4(WEs + 4 * HID + j0), w41 = ld4(WEs + 4 * HID + j0 + 4);
        float4 xr0 = ld4(XR + n * RS + j0), xr1 = ld4(XR + n * RS + j0 + 4);
        float4 acc0 = zero4(), acc1 = zero4();
        float m = -3.0e38f, sw = 0.f;
        const float* ep = g_eaT2 + ((size_t)g * NROI + n) * NROI * 8;
        const float* XLj = XL + j0;
        const float* ATTj = ATT + j0;

        #pragma unroll 4
        for (int s = 0; s < NROI; s++) {
            float4 E = ld4(ep + s * 8);
            float e4 = __ldg(ep + s * 8 + 4);
            float4 p0 = zero4(), p1 = zero4();
            p0 = fma4(E.x, w00, p0);  p1 = fma4(E.x, w01, p1);
            p0 = fma4(E.y, w10, p0);  p1 = fma4(E.y, w11, p1);
            p0 = fma4(E.z, w20, p0);  p1 = fma4(E.z, w21, p1);
            p0 = fma4(E.w, w30, p0);  p1 = fma4(E.w, w31, p1);
            p0 = fma4(e4,  w40, p0);  p1 = fma4(e4,  w41, p1);
            const float* xlr = XLj + s * RS;
            float4 xl0 = ld4(xlr), xl1 = ld4(xlr + 4);
            float4 lk0 = leaky4(add4(add4(xl0, xr0), p0));
            float4 lk1 = leaky4(add4(add4(xl1, xr1), p1));
            float4 at0 = ld4(ATTj), at1 = ld4(ATTj + 4);
            float part = 0.f;
            part = fmaf(at0.x, lk0.x, part); part = fmaf(at0.y, lk0.y, part);
            part = fmaf(at0.z, lk0.z, part); part = fmaf(at0.w, lk0.w, part);
            part = fmaf(at1.x, lk1.x, part); part = fmaf(at1.y, lk1.y, part);
            part = fmaf(at1.z, lk1.z, part); part = fmaf(at1.w, lk1.w, part);
            part += __shfl_xor_sync(0xffffffffu, part, 1);
            part += __shfl_xor_sync(0xffffffffu, part, 2);
            part += __shfl_xor_sync(0xffffffffu, part, 4);

            float nm = fmaxf(m, part);
            float fac = __expf(m - nm);
            float w   = __expf(part - nm);
            sw = sw * fac + w;
            acc0 = fma4(w, xl0, scale4(acc0, fac));
            acc1 = fma4(w, xl1, scale4(acc1, fac));
            m = nm;
        }

        float inv = 1.f / (sw + 1e-16f);
        float* og = op + ((size_t)g * NROI + n) * HID + j0;
        st4(og,     relu4(add4(scale4(acc0, inv), ld4(BI + j0))));
        st4(og + 4, relu4(add4(scale4(acc1, inv), ld4(BI + j0 + 4))));
    }
}

__global__ void __launch_bounds__(512) k_pool1(
    const float* __restrict__ W, const float* __restrict__ b,
    const float* __restrict__ w2)
{
    __shared__ __align__(16) float H[NROI * RS];
    __shared__ __align__(16) float Ws[HID * HID];
    __shared__ __align__(16) float Bs[HID];
    __shared__ __align__(16) float W2s[HID];
    int g = blockIdx.x, tid = threadIdx.x;
    const float* ing = g_hA + (size_t)g * NROI * HID;
    for (int i = tid; i < NROI * HID; i += 512)
        H[(i >> 6) * RS + (i & 63)] = ing[i];
    for (int i = tid; i < HID * HID; i += 512) Ws[i] = W[i];
    if (tid < HID) { Bs[tid] = b[tid]; W2s[tid] = w2[tid]; }
    __syncthreads();

    int nn = tid >> 2, jg = tid & 3, j0 = jg * 16;
    bool valid = (tid < 464);
    int n = valid ? nn : 0;

    float4 a[4];
    #pragma unroll
    for (int q = 0; q < 4; q++) a[q] = ld4(Bs + j0 + 4 * q);
    const float* hr = H + n * RS;
    #pragma unroll 4
    for (int c = 0; c < HID; c++) {
        float xv = hr[c];
        const float* wr = Ws + c * HID + j0;
        a[0] = fma4(xv, ld4(wr), a[0]);
        a[1] = fma4(xv, ld4(wr + 4), a[1]);
        a[2] = fma4(xv, ld4(wr + 8), a[2]);
        a[3] = fma4(xv, ld4(wr + 12), a[3]);
    }
    float part = 0.f;
    #pragma unroll
    for (int q = 0; q < 4; q++) {
        float4 w4 = ld4(W2s + j0 + 4 * q);
        part = fmaf(tanhf(a[q].x), w4.x, part);
        part = fmaf(tanhf(a[q].y), w4.y, part);
        part = fmaf(tanhf(a[q].z), w4.z, part);
        part = fmaf(tanhf(a[q].w), w4.w, part);
    }
    part += __shfl_xor_sync(0xffffffffu, part, 1);
    part += __shfl_xor_sync(0xffffffffu, part, 2);
    if (valid && jg == 0) g_t[g * NROI + nn] = part;
}

__global__ void __launch_bounds__(1024) k_pool2() {
    __shared__ float red[1024];
    int t = threadIdx.x;
    float mx = -3.0e38f;
    for (int i = t; i < NNODE; i += 1024) mx = fmaxf(mx, g_t[i]);
    red[t] = mx;
    __syncthreads();
    for (int o = 512; o > 0; o >>= 1) {
        if (t < o) red[t] = fmaxf(red[t], red[t + o]);
        __syncthreads();
    }
    float M = red[0];
    __syncthreads();
    float s = 0.f;
    for (int i = t; i < NNODE; i += 1024) s += __expf(g_t[i] - M);
    red[t] = s;
    __syncthreads();
    for (int o = 512; o > 0; o >>= 1) {
        if (t < o) red[t] += red[t + o];
        __syncthreads();
    }
    if (t == 0) { g_MS[0] = M; g_MS[1] = red[0]; }
}

__global__ void __launch_bounds__(128) k_pool3(
    const float* __restrict__ l1W, const float* __restrict__ l1b,
    const float* __restrict__ l2W, const float* __restrict__ l2b,
    float* __restrict__ out)
{
    __shared__ float wex[NROI];
    __shared__ float pooled[HID];
    __shared__ float y[NROI];
    int g = blockIdx.x, t = threadIdx.x;
    float M = g_MS[0];
    float invS = 1.f / g_MS[1];
    if (t < NROI) wex[t] = __expf(g_t[g * NROI + t] - M) * invS;
    __syncthreads();
    if (t < HID) {
        float s = 0.f;
        const float* hg = g_hA + (size_t)g * NROI * HID;
        for (int n = 0; n < NROI; n++) s = fmaf(hg[n * HID + t], wex[n], s);
        pooled[t] = s;
    }
    __syncthreads();
    if (t < NROI) {
        float a = l1b[t];
        for (int c = 0; c < HID; c++) a = fmaf(pooled[c], l1W[c * INCH + t], a);
        y[t] = fmaxf(a, 0.f);
    }
    __syncthreads();
    if (t < 2) {
        float o = l2b[t];
        for (int j = 0; j < NROI; j++) o = fmaf(y[j], l2W[j * 2 + t], o);
        out[g * 2 + t] = o;
    }
}

extern "C" void kernel_launch(void* const* d_in, const int* in_sizes, int n_in,
                              void* d_out, int out_size)
{
    const float* x    = (const float*)d_in[0];
    const float* ea   = (const float*)d_in[1];
    const float* emb  = (const float*)d_in[2];
    const float* encW = (const float*)d_in[3];
    const float* encb = (const float*)d_in[4];
    const float* bng  = (const float*)d_in[5];
    const float* bnb  = (const float*)d_in[6];
    const float* gWe  = (const float*)d_in[7];
    const float* gbe  = (const float*)d_in[8];
    const float* gW1  = (const float*)d_in[9];
    const float* gb1  = (const float*)d_in[10];
    const float* gW2  = (const float*)d_in[11];
    const float* gb2  = (const float*)d_in[12];
    const float* aWl  = (const float*)d_in[13];
    const float* abl  = (const float*)d_in[14];
    const float* aWr  = (const float*)d_in[15];
    const float* abr  = (const float*)d_in[16];
    const float* aat  = (const float*)d_in[17];
    const float* aWe  = (const float*)d_in[18];
    const float* abi  = (const float*)d_in[19];
    const float* pW1  = (const float*)d_in[20];
    const float* pb1  = (const float*)d_in[21];
    const float* pw2  = (const float*)d_in[22];
    const float* l1W  = (const float*)d_in[23];
    const float* l1b  = (const float*)d_in[24];
    const float* l2W  = (const float*)d_in[25];
    const float* l2b  = (const float*)d_in[26];
    const int*   gid  = (const int*)d_in[29];
    float* out = (float*)d_out;

    const int smEnc  = (NROI * CIN + CIN * HID + NROI * RS + HID) * 4;
    const int smGine = (2 * NROI * RS + 2 * HID * HID + EDIM * HID + 3 * HID) * 4;
    const int smGat  = (3 * NROI * RS + HID * HID + EDIM * HID + 3 * HID) * 4;
    cudaFuncSetAttribute(k_encode, cudaFuncAttributeMaxDynamicSharedMemorySize, smEnc);
    cudaFuncSetAttribute(k_gine,   cudaFuncAttributeMaxDynamicSharedMemorySize, smGine);
    cudaFuncSetAttribute(k_gat,    cudaFuncAttributeMaxDynamicSharedMemorySize, smGat);

    k_init<<<1, 64>>>();
    k_etrans<<<(NGR * EPG + 255) / 256, 256>>>(ea);
    k_encode<<<NGR, THR, smEnc>>>(x, emb, gid, encW, encb);
    k_bnfin<<<1, 64>>>(bng, bnb);
    k_gine<<<NGR, THR, smGine>>>(gWe, gbe, gW1, gb1, gW2, gb2);
    k_gat<<<NGR, THR, smGat>>>(0, aWl, abl, aWr, abr, aat, aWe, abi);
    k_gat<<<NGR, THR, smGat>>>(1, aWl, abl, aWr, abr, aat, aWe, abi);
    k_pool1<<<NGR, 512>>>(pW1, pb1, pw2);
    k_pool2<<<1, 1024>>>();
    k_pool3<<<NGR, 128>>>(l1W, l1b, l2W, l2b, out);
}

// round 6
// speedup vs baseline: 2.5102x; 2.5102x over previous
#include <cuda_runtime.h>
#include <math.h>

#define NROI 116
#define NGR  128
#define HID  64
#define EDIM 5
#define INCH 116
#define EMBD 16
#define CIN  (INCH + EMBD)
#define EPG  (NROI * NROI)
#define NNODE (NROI * NGR)
#define RS   68
#define THR  928
#define GTHR 512
#define CH   29
#define NCHUNK 4
#define ESF  (CH * NROI * EDIM)   /* 16820 floats per chunk */
#define ESF4 (ESF / 4)            /* 4205 float4 */

__device__ float g_hpre[NNODE * HID];
__device__ float g_hA[NNODE * HID];
__device__ float g_hB[NNODE * HID];
__device__ float g_sum[HID];
__device__ float g_sumsq[HID];
__device__ float g_scale[HID];
__device__ float g_shift[HID];
__device__ float g_t[NNODE];
__device__ float g_MS[2];

__device__ __forceinline__ float4 ld4(const float* p) { return *reinterpret_cast<const float4*>(p); }
__device__ __forceinline__ void st4(float* p, float4 v) { *reinterpret_cast<float4*>(p) = v; }
__device__ __forceinline__ float4 fma4(float a, float4 b, float4 c) {
    c.x = fmaf(a, b.x, c.x); c.y = fmaf(a, b.y, c.y);
    c.z = fmaf(a, b.z, c.z); c.w = fmaf(a, b.w, c.w); return c;
}
__device__ __forceinline__ float4 add4(float4 a, float4 b) {
    a.x += b.x; a.y += b.y; a.z += b.z; a.w += b.w; return a;
}
__device__ __forceinline__ float4 sub4(float4 a, float4 b) {
    a.x -= b.x; a.y -= b.y; a.z -= b.z; a.w -= b.w; return a;
}
__device__ __forceinline__ float4 relu4(float4 a) {
    a.x = fmaxf(a.x, 0.f); a.y = fmaxf(a.y, 0.f);
    a.z = fmaxf(a.z, 0.f); a.w = fmaxf(a.w, 0.f); return a;
}
__device__ __forceinline__ float4 scale4(float4 a, float f) {
    a.x *= f; a.y *= f; a.z *= f; a.w *= f; return a;
}
__device__ __forceinline__ float4 leaky4(float4 u) {
    float4 r;
    r.x = fmaxf(u.x, 0.f) + 0.2f * fminf(u.x, 0.f);
    r.y = fmaxf(u.y, 0.f) + 0.2f * fminf(u.y, 0.f);
    r.z = fmaxf(u.z, 0.f) + 0.2f * fminf(u.z, 0.f);
    r.w = fmaxf(u.w, 0.f) + 0.2f * fminf(u.w, 0.f);
    return r;
}
__device__ __forceinline__ float4 zero4() { return make_float4(0.f, 0.f, 0.f, 0.f); }

__global__ void k_init() {
    int t = threadIdx.x;
    if (t < HID) { g_sum[t] = 0.f; g_sumsq[t] = 0.f; }
}

__global__ void __launch_bounds__(THR) k_encode(
    const float* __restrict__ x, const float* __restrict__ emb,
    const int* __restrict__ gid,
    const float* __restrict__ W, const float* __restrict__ b)
{
    extern __shared__ float sm[];
    float* XC = sm;
    float* WE = XC + NROI * CIN;
    float* HS = WE + CIN * HID;
    float* BS = HS + NROI * RS;
    int g = blockIdx.x, tid = threadIdx.x;

    for (int i = tid; i < CIN * HID; i += THR) WE[i] = W[i];
    if (tid < HID) BS[tid] = b[tid];
    const float* xg = x + (size_t)g * NROI * INCH;
    for (int i = tid; i < NROI * INCH; i += THR) {
        int n = i / INCH, c = i - n * INCH;
        XC[n * CIN + c] = xg[i];
    }
    for (int i = tid; i < NROI * EMBD; i += THR) {
        int n = i / EMBD, k = i - n * EMBD;
        XC[n * CIN + INCH + k] = emb[gid[g * NROI + n] * EMBD + k];
    }
    __syncthreads();

    int n = tid >> 3, jg = tid & 7, j0 = jg * 8;
    {
        float4 a0 = ld4(BS + j0), a1 = ld4(BS + j0 + 4);
        const float* xr = XC + n * CIN;
        #pragma unroll 4
        for (int c = 0; c < CIN; c++) {
            float xv = xr[c];
            const float* wr = WE + c * HID + j0;
            a0 = fma4(xv, ld4(wr), a0);
            a1 = fma4(xv, ld4(wr + 4), a1);
        }
        a0 = relu4(a0); a1 = relu4(a1);
        float* hp = g_hpre + ((size_t)g * NROI + n) * HID + j0;
        float* hs = HS + n * RS + j0;
        st4(hp, a0); st4(hp + 4, a1);
        st4(hs, a0); st4(hs + 4, a1);
    }
    __syncthreads();

    if (tid < HID) {
        float s1 = 0.f, s2 = 0.f;
        for (int r = 0; r < NROI; r++) {
            float v = HS[r * RS + tid];
            s1 += v; s2 += v * v;
        }
        atomicAdd(&g_sum[tid], s1);
        atomicAdd(&g_sumsq[tid], s2);
    }
}

__global__ void k_bnfin(const float* __restrict__ gg, const float* __restrict__ gb) {
    int j = threadIdx.x;
    if (j < HID) {
        const float invN = 1.0f / (float)NNODE;
        float mu  = g_sum[j] * invN;
        float var = g_sumsq[j] * invN - mu * mu;
        float sc  = gg[j] * rsqrtf(var + 1e-5f);
        g_scale[j] = sc;
        g_shift[j] = gb[j] - mu * sc;
    }
}

// ---------------- GINE: edge chunks staged in smem ----------------
__global__ void __launch_bounds__(THR) k_gine(
    const float* __restrict__ ea,
    const float* __restrict__ We, const float* __restrict__ be,
    const float* __restrict__ W1, const float* __restrict__ b1,
    const float* __restrict__ W2, const float* __restrict__ b2)
{
    extern __shared__ float sm[];
    float* H   = sm;                    // NROI*RS  : H' = BN(h) + be
    float* AG  = H + NROI * RS;         // NROI*RS
    float* W1s = AG + NROI * RS;        // 4096
    float* W2s = W1s + HID * HID;       // 4096
    float* WEs = W2s + HID * HID;       // 320
    float* ES  = WEs + EDIM * HID;      // ESF
    float* BEs = ES + ESF;              // 64
    float* B1s = BEs + HID;             // 64
    float* B2s = B1s + HID;             // 64
    int g = blockIdx.x, tid = threadIdx.x;

    for (int i = tid; i < HID * HID; i += THR) { W1s[i] = W1[i]; W2s[i] = W2[i]; }
    if (tid < EDIM * HID) WEs[tid] = We[tid];
    if (tid < HID) { BEs[tid] = be[tid]; B1s[tid] = b1[tid]; B2s[tid] = b2[tid]; }
    const float* hp = g_hpre + (size_t)g * NROI * HID;
    for (int i = tid; i < NROI * HID; i += THR) {
        int n = i >> 6, j = i & 63;
        H[n * RS + j] = hp[i] * g_scale[j] + g_shift[j] + __ldg(be + j);
    }
    __syncthreads();

    int d = tid >> 3, jg = tid & 7, j0 = jg * 8;

    // loop-invariant weights in registers
    float4 w00 = ld4(WEs + 0 * HID + j0), w01 = ld4(WEs + 0 * HID + j0 + 4);
    float4 w10 = ld4(WEs + 1 * HID + j0), w11 = ld4(WEs + 1 * HID + j0 + 4);
    float4 w20 = ld4(WEs + 2 * HID + j0), w21 = ld4(WEs + 2 * HID + j0 + 4);
    float4 w30 = ld4(WEs + 3 * HID + j0), w31 = ld4(WEs + 3 * HID + j0 + 4);
    float4 w40 = ld4(WEs + 4 * HID + j0), w41 = ld4(WEs + 4 * HID + j0 + 4);
    float4 acc0 = zero4(), acc1 = zero4();

    const float4* eaq = reinterpret_cast<const float4*>(ea + (size_t)g * EPG * EDIM);
    for (int c = 0; c < NCHUNK; c++) {
        const float4* src = eaq + c * ESF4;
        float4* es4 = reinterpret_cast<float4*>(ES);
        for (int i = tid; i < ESF4; i += THR) es4[i] = src[i];
        __syncthreads();

        const float* hr  = H + j0 + (c * CH) * RS;
        const float* ero = ES + d * EDIM;
        #pragma unroll 1
        for (int sl = 0; sl < CH; sl++) {
            float e0 = ero[0], e1 = ero[1], e2 = ero[2], e3 = ero[3], e4 = ero[4];
            float4 p0 = zero4(), p1 = zero4();
            p0 = fma4(e0, w00, p0);  p1 = fma4(e0, w01, p1);
            p0 = fma4(e1, w10, p0);  p1 = fma4(e1, w11, p1);
            p0 = fma4(e2, w20, p0);  p1 = fma4(e2, w21, p1);
            p0 = fma4(e3, w30, p0);  p1 = fma4(e3, w31, p1);
            p0 = fma4(e4, w40, p0);  p1 = fma4(e4, w41, p1);
            acc0 = add4(acc0, relu4(add4(ld4(hr), p0)));
            acc1 = add4(acc1, relu4(add4(ld4(hr + 4), p1)));
            hr  += RS;
            ero += NROI * EDIM;
        }
        __syncthreads();
    }

    {   // AG = acc + h_d   (h_d = H'_d - be)
        float4 be0 = ld4(BEs + j0), be1 = ld4(BEs + j0 + 4);
        const float* hd = H + d * RS + j0;
        float* agr = AG + d * RS + j0;
        st4(agr,     add4(acc0, sub4(ld4(hd), be0)));
        st4(agr + 4, add4(acc1, sub4(ld4(hd + 4), be1)));
    }
    __syncthreads();

    {   // MLP layer 1
        float4 a0 = ld4(B1s + j0), a1 = ld4(B1s + j0 + 4);
        const float* inr = AG + d * RS;
        #pragma unroll 4
        for (int c = 0; c < HID; c++) {
            float xv = inr[c];
            const float* wr = W1s + c * HID + j0;
            a0 = fma4(xv, ld4(wr), a0);
            a1 = fma4(xv, ld4(wr + 4), a1);
        }
        float* hr = H + d * RS + j0;
        st4(hr, relu4(a0)); st4(hr + 4, relu4(a1));
    }
    __syncthreads();

    {   // MLP layer 2 -> relu -> g_hA
        float4 a0 = ld4(B2s + j0), a1 = ld4(B2s + j0 + 4);
        const float* inr = H + d * RS;
        #pragma unroll 4
        for (int c = 0; c < HID; c++) {
            float xv = inr[c];
            const float* wr = W2s + c * HID + j0;
            a0 = fma4(xv, ld4(wr), a0);
            a1 = fma4(xv, ld4(wr + 4), a1);
        }
        float* og = g_hA + ((size_t)g * NROI + d) * HID + j0;
        st4(og, relu4(a0)); st4(og + 4, relu4(a1));
    }
}

// ---------------- GATv2: 512 threads, 2 dst per thread, smem edge chunks ----
__global__ void __launch_bounds__(GTHR) k_gat(
    int layer, const float* __restrict__ ea,
    const float* __restrict__ Wl_all, const float* __restrict__ bl_all,
    const float* __restrict__ Wr_all, const float* __restrict__ br_all,
    const float* __restrict__ att_all, const float* __restrict__ We_all,
    const float* __restrict__ bias_all)
{
    const float* in  = (layer == 0) ? g_hA : g_hB;
    float*       op  = (layer == 0) ? g_hB : g_hA;
    const float* Wl  = Wl_all  + layer * HID * HID;
    const float* bl  = bl_all  + layer * HID;
    const float* Wr  = Wr_all  + layer * HID * HID;
    const float* br  = br_all  + layer * HID;
    const float* att = att_all + layer * HID;
    const float* Wee = We_all  + layer * EDIM * HID;
    const float* bia = bias_all + layer * HID;

    extern __shared__ float sm[];
    float* H   = sm;                    // NROI*RS
    float* XL  = H + NROI * RS;         // NROI*RS
    float* XR  = XL + NROI * RS;        // NROI*RS
    float* Ws  = XR + NROI * RS;        // 4096
    float* WEs = Ws + HID * HID;        // 320
    float* ES  = WEs + EDIM * HID;      // ESF
    float* ATT = ES + ESF;              // 64
    float* BV  = ATT + HID;             // 64
    float* BI  = BV + HID;              // 64
    int g = blockIdx.x, tid = threadIdx.x;

    const float* ing = in + (size_t)g * NROI * HID;
    for (int i = tid; i < NROI * HID; i += GTHR)
        H[(i >> 6) * RS + (i & 63)] = ing[i];
    for (int i = tid; i < HID * HID; i += GTHR) Ws[i] = Wl[i];
    if (tid < EDIM * HID) WEs[tid] = Wee[tid];
    if (tid < HID) { ATT[tid] = att[tid]; BV[tid] = bl[tid]; BI[tid] = bia[tid]; }
    __syncthreads();

    int nb = tid >> 3, jg = tid & 7, j0 = jg * 8;

    // XL for all 116 nodes (two batches)
    #pragma unroll 1
    for (int batch = 0; batch < 2; batch++) {
        int n = nb + batch * 64;
        if (n < NROI) {
            float4 a0 = ld4(BV + j0), a1 = ld4(BV + j0 + 4);
            const float* hr = H + n * RS;
            #pragma unroll 4
            for (int c = 0; c < HID; c++) {
                float xv = hr[c];
                const float* wr = Ws + c * HID + j0;
                a0 = fma4(xv, ld4(wr), a0);
                a1 = fma4(xv, ld4(wr + 4), a1);
            }
            float* o = XL + n * RS + j0;
            st4(o, a0); st4(o + 4, a1);
        }
    }
    __syncthreads();
    for (int i = tid; i < HID * HID; i += GTHR) Ws[i] = Wr[i];
    if (tid < HID) BV[tid] = br[tid];
    __syncthreads();
    // XR for all 116 nodes
    #pragma unroll 1
    for (int batch = 0; batch < 2; batch++) {
        int n = nb + batch * 64;
        if (n < NROI) {
            float4 a0 = ld4(BV + j0), a1 = ld4(BV + j0 + 4);
            const float* hr = H + n * RS;
            #pragma unroll 4
            for (int c = 0; c < HID; c++) {
                float xv = hr[c];
                const float* wr = Ws + c * HID + j0;
                a0 = fma4(xv, ld4(wr), a0);
                a1 = fma4(xv, ld4(wr + 4), a1);
            }
            float* o = XR + n * RS + j0;
            st4(o, a0); st4(o + 4, a1);
        }
    }
    __syncthreads();

    // edge loop: this thread owns dst d0 and d1 = d0+58
    int dl = tid >> 3;
    int d0 = (dl < 58) ? dl : 57;
    int d1 = d0 + 58;

    float4 w00 = ld4(WEs + 0 * HID + j0), w01 = ld4(WEs + 0 * HID + j0 + 4);
    float4 w10 = ld4(WEs + 1 * HID + j0), w11 = ld4(WEs + 1 * HID + j0 + 4);
    float4 w20 = ld4(WEs + 2 * HID + j0), w21 = ld4(WEs + 2 * HID + j0 + 4);
    float4 w30 = ld4(WEs + 3 * HID + j0), w31 = ld4(WEs + 3 * HID + j0 + 4);
    float4 w40 = ld4(WEs + 4 * HID + j0), w41 = ld4(WEs + 4 * HID + j0 + 4);
    float4 at0 = ld4(ATT + j0), at1 = ld4(ATT + j0 + 4);
    float4 xa0 = ld4(XR + d0 * RS + j0), xa1 = ld4(XR + d0 * RS + j0 + 4);
    float4 xb0 = ld4(XR + d1 * RS + j0), xb1 = ld4(XR + d1 * RS + j0 + 4);
    float4 accA0 = zero4(), accA1 = zero4(), accB0 = zero4(), accB1 = zero4();
    float mA = -3.0e38f, swA = 0.f, mB = -3.0e38f, swB = 0.f;

    const float4* eaq = reinterpret_cast<const float4*>(ea + (size_t)g * EPG * EDIM);
    for (int c = 0; c < NCHUNK; c++) {
        const float4* src = eaq + c * ESF4;
        float4* es4 = reinterpret_cast<float4*>(ES);
        for (int i = tid; i < ESF4; i += GTHR) es4[i] = src[i];
        __syncthreads();

        const float* xlp = XL + j0 + (c * CH) * RS;
        const float* ero = ES;
        #pragma unroll 1
        for (int sl = 0; sl < CH; sl++) {
            float4 xl0 = ld4(xlp), xl1 = ld4(xlp + 4);
            const float* eA = ero + d0 * EDIM;
            const float* eB = ero + d1 * EDIM;
            float a0v = eA[0], a1v = eA[1], a2v = eA[2], a3v = eA[3], a4v = eA[4];
            float b0v = eB[0], b1v = eB[1], b2v = eB[2], b3v = eB[3], b4v = eB[4];

            float4 pa0 = zero4(), pa1 = zero4();
            pa0 = fma4(a0v, w00, pa0);  pa1 = fma4(a0v, w01, pa1);
            pa0 = fma4(a1v, w10, pa0);  pa1 = fma4(a1v, w11, pa1);
            pa0 = fma4(a2v, w20, pa0);  pa1 = fma4(a2v, w21, pa1);
            pa0 = fma4(a3v, w30, pa0);  pa1 = fma4(a3v, w31, pa1);
            pa0 = fma4(a4v, w40, pa0);  pa1 = fma4(a4v, w41, pa1);
            float4 pb0 = zero4(), pb1 = zero4();
            pb0 = fma4(b0v, w00, pb0);  pb1 = fma4(b0v, w01, pb1);
            pb0 = fma4(b1v, w10, pb0);  pb1 = fma4(b1v, w11, pb1);
            pb0 = fma4(b2v, w20, pb0);  pb1 = fma4(b2v, w21, pb1);
            pb0 = fma4(b3v, w30, pb0);  pb1 = fma4(b3v, w31, pb1);
            pb0 = fma4(b4v, w40, pb0);  pb1 = fma4(b4v, w41, pb1);

            float4 lkA0 = leaky4(add4(add4(xl0, xa0), pa0));
            float4 lkA1 = leaky4(add4(add4(xl1, xa1), pa1));
            float4 lkB0 = leaky4(add4(add4(xl0, xb0), pb0));
            float4 lkB1 = leaky4(add4(add4(xl1, xb1), pb1));

            float pA = 0.f, pB = 0.f;
            pA = fmaf(at0.x, lkA0.x, pA); pA = fmaf(at0.y, lkA0.y, pA);
            pA = fmaf(at0.z, lkA0.z, pA); pA = fmaf(at0.w, lkA0.w, pA);
            pA = fmaf(at1.x, lkA1.x, pA); pA = fmaf(at1.y, lkA1.y, pA);
            pA = fmaf(at1.z, lkA1.z, pA); pA = fmaf(at1.w, lkA1.w, pA);
            pB = fmaf(at0.x, lkB0.x, pB); pB = fmaf(at0.y, lkB0.y, pB);
            pB = fmaf(at0.z, lkB0.z, pB); pB = fmaf(at0.w, lkB0.w, pB);
            pB = fmaf(at1.x, lkB1.x, pB); pB = fmaf(at1.y, lkB1.y, pB);
            pB = fmaf(at1.z, lkB1.z, pB); pB = fmaf(at1.w, lkB1.w, pB);

            pA += __shfl_xor_sync(0xffffffffu, pA, 1);
            pB += __shfl_xor_sync(0xffffffffu, pB, 1);
            pA += __shfl_xor_sync(0xffffffffu, pA, 2);
            pB += __shfl_xor_sync(0xffffffffu, pB, 2);
            pA += __shfl_xor_sync(0xffffffffu, pA, 4);
            pB += __shfl_xor_sync(0xffffffffu, pB, 4);

            float nmA = fmaxf(mA, pA);
            float fA  = __expf(mA - nmA);
            float wA  = __expf(pA - nmA);
            swA = swA * fA + wA;
            accA0 = fma4(wA, xl0, scale4(accA0, fA));
            accA1 = fma4(wA, xl1, scale4(accA1, fA));
            mA = nmA;

            float nmB = fmaxf(mB, pB);
            float fB  = __expf(mB - nmB);
            float wB  = __expf(pB - nmB);
            swB = swB * fB + wB;
            accB0 = fma4(wB, xl0, scale4(accB0, fB));
            accB1 = fma4(wB, xl1, scale4(accB1, fB));
            mB = nmB;

            xlp += RS;
            ero += NROI * EDIM;
        }
        __syncthreads();
    }

    if (dl < 58) {
        float4 bi0 = ld4(BI + j0), bi1 = ld4(BI + j0 + 4);
        float invA = 1.f / (swA + 1e-16f);
        float invB = 1.f / (swB + 1e-16f);
        float* ogA = op + ((size_t)g * NROI + d0) * HID + j0;
        float* ogB = op + ((size_t)g * NROI + d1) * HID + j0;
        st4(ogA,     relu4(add4(scale4(accA0, invA), bi0)));
        st4(ogA + 4, relu4(add4(scale4(accA1, invA), bi1)));
        st4(ogB,     relu4(add4(scale4(accB0, invB), bi0)));
        st4(ogB + 4, relu4(add4(scale4(accB1, invB), bi1)));
    }
}

__global__ void __launch_bounds__(512) k_pool1(
    const float* __restrict__ W, const float* __restrict__ b,
    const float* __restrict__ w2)
{
    __shared__ __align__(16) float H[NROI * RS];
    __shared__ __align__(16) float Ws[HID * HID];
    __shared__ __align__(16) float Bs[HID];
    __shared__ __align__(16) float W2s[HID];
    int g = blockIdx.x, tid = threadIdx.x;
    const float* ing = g_hA + (size_t)g * NROI * HID;
    for (int i = tid; i < NROI * HID; i += 512)
        H[(i >> 6) * RS + (i & 63)] = ing[i];
    for (int i = tid; i < HID * HID; i += 512) Ws[i] = W[i];
    if (tid < HID) { Bs[tid] = b[tid]; W2s[tid] = w2[tid]; }
    __syncthreads();

    int nn = tid >> 2, jg = tid & 3, j0 = jg * 16;
    bool valid = (tid < 464);
    int n = valid ? nn : 0;

    float4 a[4];
    #pragma unroll
    for (int q = 0; q < 4; q++) a[q] = ld4(Bs + j0 + 4 * q);
    const float* hr = H + n * RS;
    #pragma unroll 4
    for (int c = 0; c < HID; c++) {
        float xv = hr[c];
        const float* wr = Ws + c * HID + j0;
        a[0] = fma4(xv, ld4(wr), a[0]);
        a[1] = fma4(xv, ld4(wr + 4), a[1]);
        a[2] = fma4(xv, ld4(wr + 8), a[2]);
        a[3] = fma4(xv, ld4(wr + 12), a[3]);
    }
    float part = 0.f;
    #pragma unroll
    for (int q = 0; q < 4; q++) {
        float4 w4 = ld4(W2s + j0 + 4 * q);
        part = fmaf(tanhf(a[q].x), w4.x, part);
        part = fmaf(tanhf(a[q].y), w4.y, part);
        part = fmaf(tanhf(a[q].z), w4.z, part);
        part = fmaf(tanhf(a[q].w), w4.w, part);
    }
    part += __shfl_xor_sync(0xffffffffu, part, 1);
    part += __shfl_xor_sync(0xffffffffu, part, 2);
    if (valid && jg == 0) g_t[g * NROI + nn] = part;
}

__global__ void __launch_bounds__(1024) k_pool2() {
    __shared__ float red[1024];
    int t = threadIdx.x;
    float mx = -3.0e38f;
    for (int i = t; i < NNODE; i += 1024) mx = fmaxf(mx, g_t[i]);
    red[t] = mx;
    __syncthreads();
    for (int o = 512; o > 0; o >>= 1) {
        if (t < o) red[t] = fmaxf(red[t], red[t + o]);
        __syncthreads();
    }
    float M = red[0];
    __syncthreads();
    float s = 0.f;
    for (int i = t; i < NNODE; i += 1024) s += __expf(g_t[i] - M);
    red[t] = s;
    __syncthreads();
    for (int o = 512; o > 0; o >>= 1) {
        if (t < o) red[t] += red[t + o];
        __syncthreads();
    }
    if (t == 0) { g_MS[0] = M; g_MS[1] = red[0]; }
}

__global__ void __launch_bounds__(128) k_pool3(
    const float* __restrict__ l1W, const float* __restrict__ l1b,
    const float* __restrict__ l2W, const float* __restrict__ l2b,
    float* __restrict__ out)
{
    __shared__ float wex[NROI];
    __shared__ float pooled[HID];
    __shared__ float y[NROI];
    int g = blockIdx.x, t = threadIdx.x;
    float M = g_MS[0];
    float invS = 1.f / g_MS[1];
    if (t < NROI) wex[t] = __expf(g_t[g * NROI + t] - M) * invS;
    __syncthreads();
    if (t < HID) {
        float s = 0.f;
        const float* hg = g_hA + (size_t)g * NROI * HID;
        for (int n = 0; n < NROI; n++) s = fmaf(hg[n * HID + t], wex[n], s);
        pooled[t] = s;
    }
    __syncthreads();
    if (t < NROI) {
        float a = l1b[t];
        for (int c = 0; c < HID; c++) a = fmaf(pooled[c], l1W[c * INCH + t], a);
        y[t] = fmaxf(a, 0.f);
    }
    __syncthreads();
    if (t < 2) {
        float o = l2b[t];
        for (int j = 0; j < NROI; j++) o = fmaf(y[j], l2W[j * 2 + t], o);
        out[g * 2 + t] = o;
    }
}

extern "C" void kernel_launch(void* const* d_in, const int* in_sizes, int n_in,
                              void* d_out, int out_size)
{
    const float* x    = (const float*)d_in[0];
    const float* ea   = (const float*)d_in[1];
    const float* emb  = (const float*)d_in[2];
    const float* encW = (const float*)d_in[3];
    const float* encb = (const float*)d_in[4];
    const float* bng  = (const float*)d_in[5];
    const float* bnb  = (const float*)d_in[6];
    const float* gWe  = (const float*)d_in[7];
    const float* gbe  = (const float*)d_in[8];
    const float* gW1  = (const float*)d_in[9];
    const float* gb1  = (const float*)d_in[10];
    const float* gW2  = (const float*)d_in[11];
    const float* gb2  = (const float*)d_in[12];
    const float* aWl  = (const float*)d_in[13];
    const float* abl  = (const float*)d_in[14];
    const float* aWr  = (const float*)d_in[15];
    const float* abr  = (const float*)d_in[16];
    const float* aat  = (const float*)d_in[17];
    const float* aWe  = (const float*)d_in[18];
    const float* abi  = (const float*)d_in[19];
    const float* pW1  = (const float*)d_in[20];
    const float* pb1  = (const float*)d_in[21];
    const float* pw2  = (const float*)d_in[22];
    const float* l1W  = (const float*)d_in[23];
    const float* l1b  = (const float*)d_in[24];
    const float* l2W  = (const float*)d_in[25];
    const float* l2b  = (const float*)d_in[26];
    const int*   gid  = (const int*)d_in[29];
    float* out = (float*)d_out;

    const int smEnc  = (NROI * CIN + CIN * HID + NROI * RS + HID) * 4;
    const int smGine = (2 * NROI * RS + 2 * HID * HID + EDIM * HID + ESF + 3 * HID) * 4;
    const int smGat  = (3 * NROI * RS + HID * HID + EDIM * HID + ESF + 3 * HID) * 4;
    cudaFuncSetAttribute(k_encode, cudaFuncAttributeMaxDynamicSharedMemorySize, smEnc);
    cudaFuncSetAttribute(k_gine,   cudaFuncAttributeMaxDynamicSharedMemorySize, smGine);
    cudaFuncSetAttribute(k_gat,    cudaFuncAttributeMaxDynamicSharedMemorySize, smGat);

    k_init<<<1, 64>>>();
    k_encode<<<NGR, THR, smEnc>>>(x, emb, gid, encW, encb);
    k_bnfin<<<1, 64>>>(bng, bnb);
    k_gine<<<NGR, THR, smGine>>>(ea, gWe, gbe, gW1, gb1, gW2, gb2);
    k_gat<<<NGR, GTHR, smGat>>>(0, ea, aWl, abl, aWr, abr, aat, aWe, abi);
    k_gat<<<NGR, GTHR, smGat>>>(1, ea, aWl, abl, aWr, abr, aat, aWe, abi);
    k_pool1<<<NGR, 512>>>(pW1, pb1, pw2);
    k_pool2<<<1, 1024>>>();
    k_pool3<<<NGR, 128>>>(l1W, l1b, l2W, l2b, out);
}

// round 8
// speedup vs baseline: 2.6592x; 1.0594x over previous
#include <cuda_runtime.h>
#include <math.h>

#define NROI 116
#define NGR  128
#define HID  64
#define EDIM 5
#define INCH 116
#define EMBD 16
#define CIN  (INCH + EMBD)
#define EPG  (NROI * NROI)
#define NNODE (NROI * NGR)
#define RS   68
#define THR  928
#define GTHR 512
#define CH   29
#define NCHUNK 4
#define ESF  (CH * NROI * EDIM)
#define ESF4 (ESF / 4)

typedef unsigned long long u64;

__device__ float g_hpre[NNODE * HID];
__device__ float g_hA[NNODE * HID];
__device__ float g_hB[NNODE * HID];
__device__ float g_sum[HID];
__device__ float g_sumsq[HID];
__device__ float g_scale[HID];
__device__ float g_shift[HID];
__device__ float g_t[NNODE];
__device__ float g_MS[2];

__device__ __forceinline__ float4 ld4(const float* p) { return *reinterpret_cast<const float4*>(p); }
__device__ __forceinline__ void st4(float* p, float4 v) { *reinterpret_cast<float4*>(p) = v; }
__device__ __forceinline__ float4 fma4(float a, float4 b, float4 c) {
    c.x = fmaf(a, b.x, c.x); c.y = fmaf(a, b.y, c.y);
    c.z = fmaf(a, b.z, c.z); c.w = fmaf(a, b.w, c.w); return c;
}
__device__ __forceinline__ float4 add4(float4 a, float4 b) {
    a.x += b.x; a.y += b.y; a.z += b.z; a.w += b.w; return a;
}
__device__ __forceinline__ float4 relu4(float4 a) {
    a.x = fmaxf(a.x, 0.f); a.y = fmaxf(a.y, 0.f);
    a.z = fmaxf(a.z, 0.f); a.w = fmaxf(a.w, 0.f); return a;
}
__device__ __forceinline__ float4 scale4(float4 a, float f) {
    a.x *= f; a.y *= f; a.z *= f; a.w *= f; return a;
}
__device__ __forceinline__ float4 zero4() { return make_float4(0.f, 0.f, 0.f, 0.f); }

// ---- packed f32x2 helpers ----
__device__ __forceinline__ u64 pk2(float x, float y) {
    u64 r; asm("mov.b64 %0,{%1,%2};" : "=l"(r) : "f"(x), "f"(y)); return r;
}
__device__ __forceinline__ u64 bc2(float x) { return pk2(x, x); }
__device__ __forceinline__ void up2(u64 v, float& x, float& y) {
    asm("mov.b64 {%0,%1},%2;" : "=f"(x), "=f"(y) : "l"(v));
}
__device__ __forceinline__ u64 f2fma(u64 a, u64 b, u64 c) {
    u64 r; asm("fma.rn.f32x2 %0,%1,%2,%3;" : "=l"(r) : "l"(a), "l"(b), "l"(c)); return r;
}
__device__ __forceinline__ void ld4p(const float* p, u64& a, u64& b) {
    float4 v = ld4(p); a = pk2(v.x, v.y); b = pk2(v.z, v.w);
}

// ---- cp.async ----
__device__ __forceinline__ void cpa16(void* smem_dst, const void* gsrc) {
    unsigned s = (unsigned)__cvta_generic_to_shared(smem_dst);
    asm volatile("cp.async.cg.shared.global [%0], [%1], 16;" :: "r"(s), "l"(gsrc) : "memory");
}
__device__ __forceinline__ void cpa_wait() {
    asm volatile("cp.async.commit_group;" ::: "memory");
    asm volatile("cp.async.wait_group 0;" ::: "memory");
}

__global__ void k_init() {
    int t = threadIdx.x;
    if (t < HID) { g_sum[t] = 0.f; g_sumsq[t] = 0.f; }
}

__global__ void __launch_bounds__(THR) k_encode(
    const float* __restrict__ x, const float* __restrict__ emb,
    const int* __restrict__ gid,
    const float* __restrict__ W, const float* __restrict__ b)
{
    extern __shared__ float sm[];
    float* XC = sm;
    float* WE = XC + NROI * CIN;
    float* HS = WE + CIN * HID;
    float* BS = HS + NROI * RS;
    int g = blockIdx.x, tid = threadIdx.x;

    for (int i = tid; i < CIN * HID; i += THR) WE[i] = W[i];
    if (tid < HID) BS[tid] = b[tid];
    const float* xg = x + (size_t)g * NROI * INCH;
    for (int i = tid; i < NROI * INCH; i += THR) {
        int n = i / INCH, c = i - n * INCH;
        XC[n * CIN + c] = xg[i];
    }
    for (int i = tid; i < NROI * EMBD; i += THR) {
        int n = i / EMBD, k = i - n * EMBD;
        XC[n * CIN + INCH + k] = emb[gid[g * NROI + n] * EMBD + k];
    }
    __syncthreads();

    int n = tid >> 3, jg = tid & 7, j0 = jg * 8;
    {
        float4 a0 = ld4(BS + j0), a1 = ld4(BS + j0 + 4);
        const float* xr = XC + n * CIN;
        #pragma unroll 4
        for (int c = 0; c < CIN; c++) {
            float xv = xr[c];
            const float* wr = WE + c * HID + j0;
            a0 = fma4(xv, ld4(wr), a0);
            a1 = fma4(xv, ld4(wr + 4), a1);
        }
        a0 = relu4(a0); a1 = relu4(a1);
        float* hp = g_hpre + ((size_t)g * NROI + n) * HID + j0;
        float* hs = HS + n * RS + j0;
        st4(hp, a0); st4(hp + 4, a1);
        st4(hs, a0); st4(hs + 4, a1);
    }
    __syncthreads();

    if (tid < HID) {
        float s1 = 0.f, s2 = 0.f;
        for (int r = 0; r < NROI; r++) {
            float v = HS[r * RS + tid];
            s1 += v; s2 += v * v;
        }
        atomicAdd(&g_sum[tid], s1);
        atomicAdd(&g_sumsq[tid], s2);
    }
}

__global__ void k_bnfin(const float* __restrict__ gg, const float* __restrict__ gb) {
    int j = threadIdx.x;
    if (j < HID) {
        const float invN = 1.0f / (float)NNODE;
        float mu  = g_sum[j] * invN;
        float var = g_sumsq[j] * invN - mu * mu;
        float sc  = gg[j] * rsqrtf(var + 1e-5f);
        g_scale[j] = sc;
        g_shift[j] = gb[j] - mu * sc;
    }
}

// ---------------- GINE: 512 thr, 2 dst/thread, packed projection ----------
__global__ void __launch_bounds__(GTHR) k_gine(
    const float* __restrict__ ea,
    const float* __restrict__ We, const float* __restrict__ be,
    const float* __restrict__ W1, const float* __restrict__ b1,
    const float* __restrict__ W2, const float* __restrict__ b2)
{
    extern __shared__ float sm[];
    float* H   = sm;                    // NROI*RS : BN(h) + be
    float* AG  = H + NROI * RS;
    float* W1s = AG + NROI * RS;
    float* W2s = W1s + HID * HID;
    float* WEs = W2s + HID * HID;
    float* ES  = WEs + EDIM * HID;
    float* BEs = ES + ESF;
    float* B1s = BEs + HID;
    float* B2s = B1s + HID;
    int g = blockIdx.x, tid = threadIdx.x;

    for (int i = tid; i < HID * HID; i += GTHR) { W1s[i] = W1[i]; W2s[i] = W2[i]; }
    if (tid < EDIM * HID) WEs[tid] = We[tid];
    if (tid < HID) { BEs[tid] = be[tid]; B1s[tid] = b1[tid]; B2s[tid] = b2[tid]; }
    const float* hp = g_hpre + (size_t)g * NROI * HID;
    for (int i = tid; i < NROI * HID; i += GTHR) {
        int n = i >> 6, j = i & 63;
        H[n * RS + j] = hp[i] * g_scale[j] + g_shift[j] + __ldg(be + j);
    }
    __syncthreads();

    int dl = tid >> 3, jg = tid & 7, j0 = jg * 8;
    int d0 = (dl < 58) ? dl : 57;
    int d1 = d0 + 58;

    u64 W00, W01, W02, W03, W10, W11, W12, W13, W20, W21, W22, W23,
        W30, W31, W32, W33, W40, W41, W42, W43;
    ld4p(WEs + 0 * HID + j0, W00, W01); ld4p(WEs + 0 * HID + j0 + 4, W02, W03);
    ld4p(WEs + 1 * HID + j0, W10, W11); ld4p(WEs + 1 * HID + j0 + 4, W12, W13);
    ld4p(WEs + 2 * HID + j0, W20, W21); ld4p(WEs + 2 * HID + j0 + 4, W22, W23);
    ld4p(WEs + 3 * HID + j0, W30, W31); ld4p(WEs + 3 * HID + j0 + 4, W32, W33);
    ld4p(WEs + 4 * HID + j0, W40, W41); ld4p(WEs + 4 * HID + j0 + 4, W42, W43);

    float4 accA0 = zero4(), accA1 = zero4(), accB0 = zero4(), accB1 = zero4();

    const float4* eaq = reinterpret_cast<const float4*>(ea + (size_t)g * EPG * EDIM);
    for (int c = 0; c < NCHUNK; c++) {
        const float4* src = eaq + c * ESF4;
        float4* es4 = reinterpret_cast<float4*>(ES);
        for (int i = tid; i < ESF4; i += GTHR) cpa16(es4 + i, src + i);
        cpa_wait();
        __syncthreads();

        const float* eroA = ES + d0 * EDIM;
        const float* eroB = ES + d1 * EDIM;
        const float* hr = H + j0 + (c * CH) * RS;
        float a0 = eroA[0], a1 = eroA[1], a2 = eroA[2], a3 = eroA[3], a4 = eroA[4];
        float b0 = eroB[0], b1 = eroB[1], b2 = eroB[2], b3 = eroB[3], b4 = eroB[4];

        #pragma unroll 1
        for (int sl = 0; sl < CH; sl++) {
            int adv = (sl + 1 < CH) ? NROI * EDIM : 0;
            const float* nA = eroA + adv;
            const float* nB = eroB + adv;
            float na0 = nA[0], na1 = nA[1], na2 = nA[2], na3 = nA[3], na4 = nA[4];
            float nb0 = nB[0], nb1 = nB[1], nb2 = nB[2], nb3 = nB[3], nb4 = nB[4];
            float4 h0 = ld4(hr), h1 = ld4(hr + 4);

            u64 E0 = bc2(a0), E1 = bc2(a1), E2 = bc2(a2), E3 = bc2(a3), E4 = bc2(a4);
            u64 pA0 = f2fma(E0, W00, 0ull), pA1 = f2fma(E0, W01, 0ull);
            u64 pA2 = f2fma(E0, W02, 0ull), pA3 = f2fma(E0, W03, 0ull);
            pA0 = f2fma(E1, W10, pA0); pA1 = f2fma(E1, W11, pA1);
            pA2 = f2fma(E1, W12, pA2); pA3 = f2fma(E1, W13, pA3);
            pA0 = f2fma(E2, W20, pA0); pA1 = f2fma(E2, W21, pA1);
            pA2 = f2fma(E2, W22, pA2); pA3 = f2fma(E2, W23, pA3);
            pA0 = f2fma(E3, W30, pA0); pA1 = f2fma(E3, W31, pA1);
            pA2 = f2fma(E3, W32, pA2); pA3 = f2fma(E3, W33, pA3);
            pA0 = f2fma(E4, W40, pA0); pA1 = f2fma(E4, W41, pA1);
            pA2 = f2fma(E4, W42, pA2); pA3 = f2fma(E4, W43, pA3);

            u64 F0 = bc2(b0), F1 = bc2(b1), F2 = bc2(b2), F3 = bc2(b3), F4 = bc2(b4);
            u64 pB0 = f2fma(F0, W00, 0ull), pB1 = f2fma(F0, W01, 0ull);
            u64 pB2 = f2fma(F0, W02, 0ull), pB3 = f2fma(F0, W03, 0ull);
            pB0 = f2fma(F1, W10, pB0); pB1 = f2fma(F1, W11, pB1);
            pB2 = f2fma(F1, W12, pB2); pB3 = f2fma(F1, W13, pB3);
            pB0 = f2fma(F2, W20, pB0); pB1 = f2fma(F2, W21, pB1);
            pB2 = f2fma(F2, W22, pB2); pB3 = f2fma(F2, W23, pB3);
            pB0 = f2fma(F3, W30, pB0); pB1 = f2fma(F3, W31, pB1);
            pB2 = f2fma(F3, W32, pB2); pB3 = f2fma(F3, W33, pB3);
            pB0 = f2fma(F4, W40, pB0); pB1 = f2fma(F4, W41, pB1);
            pB2 = f2fma(F4, W42, pB2); pB3 = f2fma(F4, W43, pB3);

            float q0, q1, q2, q3, q4, q5, q6, q7;
            up2(pA0, q0, q1); up2(pA1, q2, q3); up2(pA2, q4, q5); up2(pA3, q6, q7);
            accA0.x += fmaxf(h0.x + q0, 0.f); accA0.y += fmaxf(h0.y + q1, 0.f);
            accA0.z += fmaxf(h0.z + q2, 0.f); accA0.w += fmaxf(h0.w + q3, 0.f);
            accA1.x += fmaxf(h1.x + q4, 0.f); accA1.y += fmaxf(h1.y + q5, 0.f);
            accA1.z += fmaxf(h1.z + q6, 0.f); accA1.w += fmaxf(h1.w + q7, 0.f);
            up2(pB0, q0, q1); up2(pB1, q2, q3); up2(pB2, q4, q5); up2(pB3, q6, q7);
            accB0.x += fmaxf(h0.x + q0, 0.f); accB0.y += fmaxf(h0.y + q1, 0.f);
            accB0.z += fmaxf(h0.z + q2, 0.f); accB0.w += fmaxf(h0.w + q3, 0.f);
            accB1.x += fmaxf(h1.x + q4, 0.f); accB1.y += fmaxf(h1.y + q5, 0.f);
            accB1.z += fmaxf(h1.z + q6, 0.f); accB1.w += fmaxf(h1.w + q7, 0.f);

            a0 = na0; a1 = na1; a2 = na2; a3 = na3; a4 = na4;
            b0 = nb0; b1 = nb1; b2 = nb2; b3 = nb3; b4 = nb4;
            eroA = nA; eroB = nB;
            hr += RS;
        }
        __syncthreads();
    }

    if (dl < 58) {
        float4 be0 = ld4(BEs + j0), be1 = ld4(BEs + j0 + 4);
        const float* hdA = H + d0 * RS + j0;
        const float* hdB = H + d1 * RS + j0;
        float* agA = AG + d0 * RS + j0;
        float* agB = AG + d1 * RS + j0;
        float4 t;
        t = ld4(hdA);     st4(agA,     add4(accA0, make_float4(t.x - be0.x, t.y - be0.y, t.z - be0.z, t.w - be0.w)));
        t = ld4(hdA + 4); st4(agA + 4, add4(accA1, make_float4(t.x - be1.x, t.y - be1.y, t.z - be1.z, t.w - be1.w)));
        t = ld4(hdB);     st4(agB,     add4(accB0, make_float4(t.x - be0.x, t.y - be0.y, t.z - be0.z, t.w - be0.w)));
        t = ld4(hdB + 4); st4(agB + 4, add4(accB1, make_float4(t.x - be1.x, t.y - be1.y, t.z - be1.z, t.w - be1.w)));
    }
    __syncthreads();

    // MLP layer 1
    #pragma unroll 1
    for (int batch = 0; batch < 2; batch++) {
        int n = (tid >> 3) + batch * 64;
        if (n < NROI) {
            float4 a0 = ld4(B1s + j0), a1 = ld4(B1s + j0 + 4);
            const float* inr = AG + n * RS;
            #pragma unroll 4
            for (int c = 0; c < HID; c++) {
                float xv = inr[c];
                const float* wr = W1s + c * HID + j0;
                a0 = fma4(xv, ld4(wr), a0);
                a1 = fma4(xv, ld4(wr + 4), a1);
            }
            float* hr2 = H + n * RS + j0;
            st4(hr2, relu4(a0)); st4(hr2 + 4, relu4(a1));
        }
    }
    __syncthreads();

    // MLP layer 2 -> relu -> g_hA
    #pragma unroll 1
    for (int batch = 0; batch < 2; batch++) {
        int n = (tid >> 3) + batch * 64;
        if (n < NROI) {
            float4 a0 = ld4(B2s + j0), a1 = ld4(B2s + j0 + 4);
            const float* inr = H + n * RS;
            #pragma unroll 4
            for (int c = 0; c < HID; c++) {
                float xv = inr[c];
                const float* wr = W2s + c * HID + j0;
                a0 = fma4(xv, ld4(wr), a0);
                a1 = fma4(xv, ld4(wr + 4), a1);
            }
            float* og = g_hA + ((size_t)g * NROI + n) * HID + j0;
            st4(og, relu4(a0)); st4(og + 4, relu4(a1));
        }
    }
}

// ---------------- GATv2: 512 thr, 2 dst/thread, packed, ONLINE softmax -----
__global__ void __launch_bounds__(GTHR) k_gat(
    int layer, const float* __restrict__ ea,
    const float* __restrict__ Wl_all, const float* __restrict__ bl_all,
    const float* __restrict__ Wr_all, const float* __restrict__ br_all,
    const float* __restrict__ att_all, const float* __restrict__ We_all,
    const float* __restrict__ bias_all)
{
    const float* in  = (layer == 0) ? g_hA : g_hB;
    float*       op  = (layer == 0) ? g_hB : g_hA;
    const float* Wl  = Wl_all  + layer * HID * HID;
    const float* bl  = bl_all  + layer * HID;
    const float* Wr  = Wr_all  + layer * HID * HID;
    const float* br  = br_all  + layer * HID;
    const float* att = att_all + layer * HID;
    const float* Wee = We_all  + layer * EDIM * HID;
    const float* bia = bias_all + layer * HID;

    extern __shared__ float sm[];
    float* H   = sm;
    float* XL  = H + NROI * RS;
    float* XR  = XL + NROI * RS;
    float* Ws  = XR + NROI * RS;
    float* WEs = Ws + HID * HID;
    float* ES  = WEs + EDIM * HID;
    float* ATT = ES + ESF;
    float* BV  = ATT + HID;
    float* BI  = BV + HID;
    int g = blockIdx.x, tid = threadIdx.x;

    const float* ing = in + (size_t)g * NROI * HID;
    for (int i = tid; i < NROI * HID; i += GTHR)
        H[(i >> 6) * RS + (i & 63)] = ing[i];
    for (int i = tid; i < HID * HID; i += GTHR) Ws[i] = Wl[i];
    if (tid < EDIM * HID) WEs[tid] = Wee[tid];
    if (tid < HID) { ATT[tid] = att[tid]; BV[tid] = bl[tid]; BI[tid] = bia[tid]; }
    __syncthreads();

    int nb = tid >> 3, jg = tid & 7, j0 = jg * 8;

    #pragma unroll 1
    for (int batch = 0; batch < 2; batch++) {
        int n = nb + batch * 64;
        if (n < NROI) {
            float4 a0 = ld4(BV + j0), a1 = ld4(BV + j0 + 4);
            const float* hr = H + n * RS;
            #pragma unroll 4
            for (int c = 0; c < HID; c++) {
                float xv = hr[c];
                const float* wr = Ws + c * HID + j0;
                a0 = fma4(xv, ld4(wr), a0);
                a1 = fma4(xv, ld4(wr + 4), a1);
            }
            float* o = XL + n * RS + j0;
            st4(o, a0); st4(o + 4, a1);
        }
    }
    __syncthreads();
    for (int i = tid; i < HID * HID; i += GTHR) Ws[i] = Wr[i];
    if (tid < HID) BV[tid] = br[tid];
    __syncthreads();
    #pragma unroll 1
    for (int batch = 0; batch < 2; batch++) {
        int n = nb + batch * 64;
        if (n < NROI) {
            float4 a0 = ld4(BV + j0), a1 = ld4(BV + j0 + 4);
            const float* hr = H + n * RS;
            #pragma unroll 4
            for (int c = 0; c < HID; c++) {
                float xv = hr[c];
                const float* wr = Ws + c * HID + j0;
                a0 = fma4(xv, ld4(wr), a0);
                a1 = fma4(xv, ld4(wr + 4), a1);
            }
            float* o = XR + n * RS + j0;
            st4(o, a0); st4(o + 4, a1);
        }
    }
    __syncthreads();

    int dl = tid >> 3;
    int d0 = (dl < 58) ? dl : 57;
    int d1 = d0 + 58;

    u64 W00, W01, W02, W03, W10, W11, W12, W13, W20, W21, W22, W23,
        W30, W31, W32, W33, W40, W41, W42, W43;
    ld4p(WEs + 0 * HID + j0, W00, W01); ld4p(WEs + 0 * HID + j0 + 4, W02, W03);
    ld4p(WEs + 1 * HID + j0, W10, W11); ld4p(WEs + 1 * HID + j0 + 4, W12, W13);
    ld4p(WEs + 2 * HID + j0, W20, W21); ld4p(WEs + 2 * HID + j0 + 4, W22, W23);
    ld4p(WEs + 3 * HID + j0, W30, W31); ld4p(WEs + 3 * HID + j0 + 4, W32, W33);
    ld4p(WEs + 4 * HID + j0, W40, W41); ld4p(WEs + 4 * HID + j0 + 4, W42, W43);

    float4 at0 = ld4(ATT + j0), at1 = ld4(ATT + j0 + 4);
    float4 xa0 = ld4(XR + d0 * RS + j0), xa1 = ld4(XR + d0 * RS + j0 + 4);
    float4 xb0 = ld4(XR + d1 * RS + j0), xb1 = ld4(XR + d1 * RS + j0 + 4);
    float4 accA0 = zero4(), accA1 = zero4(), accB0 = zero4(), accB1 = zero4();
    float mA = -3.0e38f, swA = 0.f, mB = -3.0e38f, swB = 0.f;

    const float4* eaq = reinterpret_cast<const float4*>(ea + (size_t)g * EPG * EDIM);
    for (int c = 0; c < NCHUNK; c++) {
        const float4* src = eaq + c * ESF4;
        float4* es4 = reinterpret_cast<float4*>(ES);
        for (int i = tid; i < ESF4; i += GTHR) cpa16(es4 + i, src + i);
        cpa_wait();
        __syncthreads();

        const float* eroA = ES + d0 * EDIM;
        const float* eroB = ES + d1 * EDIM;
        const float* xlp = XL + j0 + (c * CH) * RS;
        float a0 = eroA[0], a1 = eroA[1], a2 = eroA[2], a3 = eroA[3], a4 = eroA[4];
        float b0 = eroB[0], b1 = eroB[1], b2 = eroB[2], b3 = eroB[3], b4 = eroB[4];

        #pragma unroll 1
        for (int sl = 0; sl < CH; sl++) {
            int adv = (sl + 1 < CH) ? NROI * EDIM : 0;
            const float* nA = eroA + adv;
            const float* nB = eroB + adv;
            float na0 = nA[0], na1 = nA[1], na2 = nA[2], na3 = nA[3], na4 = nA[4];
            float nb0 = nB[0], nb1 = nB[1], nb2 = nB[2], nb3 = nB[3], nb4 = nB[4];
            float4 xl0 = ld4(xlp), xl1 = ld4(xlp + 4);

            u64 E0 = bc2(a0), E1 = bc2(a1), E2 = bc2(a2), E3 = bc2(a3), E4 = bc2(a4);
            u64 pA0 = f2fma(E0, W00, 0ull), pA1 = f2fma(E0, W01, 0ull);
            u64 pA2 = f2fma(E0, W02, 0ull), pA3 = f2fma(E0, W03, 0ull);
            pA0 = f2fma(E1, W10, pA0); pA1 = f2fma(E1, W11, pA1);
            pA2 = f2fma(E1, W12, pA2); pA3 = f2fma(E1, W13, pA3);
            pA0 = f2fma(E2, W20, pA0); pA1 = f2fma(E2, W21, pA1);
            pA2 = f2fma(E2, W22, pA2); pA3 = f2fma(E2, W23, pA3);
            pA0 = f2fma(E3, W30, pA0); pA1 = f2fma(E3, W31, pA1);
            pA2 = f2fma(E3, W32, pA2); pA3 = f2fma(E3, W33, pA3);
            pA0 = f2fma(E4, W40, pA0); pA1 = f2fma(E4, W41, pA1);
            pA2 = f2fma(E4, W42, pA2); pA3 = f2fma(E4, W43, pA3);

            u64 F0 = bc2(b0), F1 = bc2(b1), F2 = bc2(b2), F3 = bc2(b3), F4 = bc2(b4);
            u64 pB0 = f2fma(F0, W00, 0ull), pB1 = f2fma(F0, W01, 0ull);
            u64 pB2 = f2fma(F0, W02, 0ull), pB3 = f2fma(F0, W03, 0ull);
            pB0 = f2fma(F1, W10, pB0); pB1 = f2fma(F1, W11, pB1);
            pB2 = f2fma(F1, W12, pB2); pB3 = f2fma(F1, W13, pB3);
            pB0 = f2fma(F2, W20, pB0); pB1 = f2fma(F2, W21, pB1);
            pB2 = f2fma(F2, W22, pB2); pB3 = f2fma(F2, W23, pB3);
            pB0 = f2fma(F3, W30, pB0); pB1 = f2fma(F3, W31, pB1);
            pB2 = f2fma(F3, W32, pB2); pB3 = f2fma(F3, W33, pB3);
            pB0 = f2fma(F4, W40, pB0); pB1 = f2fma(F4, W41, pB1);
            pB2 = f2fma(F4, W42, pB2); pB3 = f2fma(F4, W43, pB3);

            float q0, q1, q2, q3, q4, q5, q6, q7;
            float u, pA = 0.f, pB = 0.f;
            up2(pA0, q0, q1); up2(pA1, q2, q3); up2(pA2, q4, q5); up2(pA3, q6, q7);
            u = xl0.x + xa0.x + q0; pA = fmaf(at0.x, fmaxf(u, 0.f) + 0.2f * fminf(u, 0.f), pA);
            u = xl0.y + xa0.y + q1; pA = fmaf(at0.y, fmaxf(u, 0.f) + 0.2f * fminf(u, 0.f), pA);
            u = xl0.z + xa0.z + q2; pA = fmaf(at0.z, fmaxf(u, 0.f) + 0.2f * fminf(u, 0.f), pA);
            u = xl0.w + xa0.w + q3; pA = fmaf(at0.w, fmaxf(u, 0.f) + 0.2f * fminf(u, 0.f), pA);
            u = xl1.x + xa1.x + q4; pA = fmaf(at1.x, fmaxf(u, 0.f) + 0.2f * fminf(u, 0.f), pA);
            u = xl1.y + xa1.y + q5; pA = fmaf(at1.y, fmaxf(u, 0.f) + 0.2f * fminf(u, 0.f), pA);
            u = xl1.z + xa1.z + q6; pA = fmaf(at1.z, fmaxf(u, 0.f) + 0.2f * fminf(u, 0.f), pA);
            u = xl1.w + xa1.w + q7; pA = fmaf(at1.w, fmaxf(u, 0.f) + 0.2f * fminf(u, 0.f), pA);
            up2(pB0, q0, q1); up2(pB1, q2, q3); up2(pB2, q4, q5); up2(pB3, q6, q7);
            u = xl0.x + xb0.x + q0; pB = fmaf(at0.x, fmaxf(u, 0.f) + 0.2f * fminf(u, 0.f), pB);
            u = xl0.y + xb0.y + q1; pB = fmaf(at0.y, fmaxf(u, 0.f) + 0.2f * fminf(u, 0.f), pB);
            u = xl0.z + xb0.z + q2; pB = fmaf(at0.z, fmaxf(u, 0.f) + 0.2f * fminf(u, 0.f), pB);
            u = xl0.w + xb0.w + q3; pB = fmaf(at0.w, fmaxf(u, 0.f) + 0.2f * fminf(u, 0.f), pB);
            u = xl1.x + xb1.x + q4; pB = fmaf(at1.x, fmaxf(u, 0.f) + 0.2f * fminf(u, 0.f), pB);
            u = xl1.y + xb1.y + q5; pB = fmaf(at1.y, fmaxf(u, 0.f) + 0.2f * fminf(u, 0.f), pB);
            u = xl1.z + xb1.z + q6; pB = fmaf(at1.z, fmaxf(u, 0.f) + 0.2f * fminf(u, 0.f), pB);
            u = xl1.w + xb1.w + q7; pB = fmaf(at1.w, fmaxf(u, 0.f) + 0.2f * fminf(u, 0.f), pB);

            pA += __shfl_xor_sync(0xffffffffu, pA, 1);
            pB += __shfl_xor_sync(0xffffffffu, pB, 1);
            pA += __shfl_xor_sync(0xffffffffu, pA, 2);
            pB += __shfl_xor_sync(0xffffffffu, pB, 2);
            pA += __shfl_xor_sync(0xffffffffu, pA, 4);
            pB += __shfl_xor_sync(0xffffffffu, pB, 4);

            // online (max-subtracted) softmax — scores can reach O(100)
            float nmA = fmaxf(mA, pA);
            float fA  = __expf(mA - nmA);
            float wA  = __expf(pA - nmA);
            swA = swA * fA + wA;
            accA0 = fma4(wA, xl0, scale4(accA0, fA));
            accA1 = fma4(wA, xl1, scale4(accA1, fA));
            mA = nmA;

            float nmB = fmaxf(mB, pB);
            float fB  = __expf(mB - nmB);
            float wB  = __expf(pB - nmB);
            swB = swB * fB + wB;
            accB0 = fma4(wB, xl0, scale4(accB0, fB));
            accB1 = fma4(wB, xl1, scale4(accB1, fB));
            mB = nmB;

            a0 = na0; a1 = na1; a2 = na2; a3 = na3; a4 = na4;
            b0 = nb0; b1 = nb1; b2 = nb2; b3 = nb3; b4 = nb4;
            eroA = nA; eroB = nB;
            xlp += RS;
        }
        __syncthreads();
    }

    if (dl < 58) {
        float4 bi0 = ld4(BI + j0), bi1 = ld4(BI + j0 + 4);
        float invA = 1.f / (swA + 1e-16f);
        float invB = 1.f / (swB + 1e-16f);
        float* ogA = op + ((size_t)g * NROI + d0) * HID + j0;
        float* ogB = op + ((size_t)g * NROI + d1) * HID + j0;
        st4(ogA,     relu4(add4(scale4(accA0, invA), bi0)));
        st4(ogA + 4, relu4(add4(scale4(accA1, invA), bi1)));
        st4(ogB,     relu4(add4(scale4(accB0, invB), bi0)));
        st4(ogB + 4, relu4(add4(scale4(accB1, invB), bi1)));
    }
}

__global__ void __launch_bounds__(512) k_pool1(
    const float* __restrict__ W, const float* __restrict__ b,
    const float* __restrict__ w2)
{
    __shared__ __align__(16) float H[NROI * RS];
    __shared__ __align__(16) float Ws[HID * HID];
    __shared__ __align__(16) float Bs[HID];
    __shared__ __align__(16) float W2s[HID];
    int g = blockIdx.x, tid = threadIdx.x;
    const float* ing = g_hA + (size_t)g * NROI * HID;
    for (int i = tid; i < NROI * HID; i += 512)
        H[(i >> 6) * RS + (i & 63)] = ing[i];
    for (int i = tid; i < HID * HID; i += 512) Ws[i] = W[i];
    if (tid < HID) { Bs[tid] = b[tid]; W2s[tid] = w2[tid]; }
    __syncthreads();

    int nn = tid >> 2, jg = tid & 3, j0 = jg * 16;
    bool valid = (tid < 464);
    int n = valid ? nn : 0;

    float4 a[4];
    #pragma unroll
    for (int q = 0; q < 4; q++) a[q] = ld4(Bs + j0 + 4 * q);
    const float* hr = H + n * RS;
    #pragma unroll 4
    for (int c = 0; c < HID; c++) {
        float xv = hr[c];
        const float* wr = Ws + c * HID + j0;
        a[0] = fma4(xv, ld4(wr), a[0]);
        a[1] = fma4(xv, ld4(wr + 4), a[1]);
        a[2] = fma4(xv, ld4(wr + 8), a[2]);
        a[3] = fma4(xv, ld4(wr + 12), a[3]);
    }
    float part = 0.f;
    #pragma unroll
    for (int q = 0; q < 4; q++) {
        float4 w4 = ld4(W2s + j0 + 4 * q);
        part = fmaf(tanhf(a[q].x), w4.x, part);
        part = fmaf(tanhf(a[q].y), w4.y, part);
        part = fmaf(tanhf(a[q].z), w4.z, part);
        part = fmaf(tanhf(a[q].w), w4.w, part);
    }
    part += __shfl_xor_sync(0xffffffffu, part, 1);
    part += __shfl_xor_sync(0xffffffffu, part, 2);
    if (valid && jg == 0) g_t[g * NROI + nn] = part;
}

__global__ void __launch_bounds__(1024) k_pool2() {
    __shared__ float red[1024];
    int t = threadIdx.x;
    float mx = -3.0e38f;
    for (int i = t; i < NNODE; i += 1024) mx = fmaxf(mx, g_t[i]);
    red[t] = mx;
    __syncthreads();
    for (int o = 512; o > 0; o >>= 1) {
        if (t < o) red[t] = fmaxf(red[t], red[t + o]);
        __syncthreads();
    }
    float M = red[0];
    __syncthreads();
    float s = 0.f;
    for (int i = t; i < NNODE; i += 1024) s += __expf(g_t[i] - M);
    red[t] = s;
    __syncthreads();
    for (int o = 512; o > 0; o >>= 1) {
        if (t < o) red[t] += red[t + o];
        __syncthreads();
    }
    if (t == 0) { g_MS[0] = M; g_MS[1] = red[0]; }
}

__global__ void __launch_bounds__(128) k_pool3(
    const float* __restrict__ l1W, const float* __restrict__ l1b,
    const float* __restrict__ l2W, const float* __restrict__ l2b,
    float* __restrict__ out)
{
    __shared__ float wex[NROI];
    __shared__ float pooled[HID];
    __shared__ float y[NROI];
    int g = blockIdx.x, t = threadIdx.x;
    float M = g_MS[0];
    float invS = 1.f / g_MS[1];
    if (t < NROI) wex[t] = __expf(g_t[g * NROI + t] - M) * invS;
    __syncthreads();
    if (t < HID) {
        float s = 0.f;
        const float* hg = g_hA + (size_t)g * NROI * HID;
        for (int n = 0; n < NROI; n++) s = fmaf(hg[n * HID + t], wex[n], s);
        pooled[t] = s;
    }
    __syncthreads();
    if (t < NROI) {
        float a = l1b[t];
        for (int c = 0; c < HID; c++) a = fmaf(pooled[c], l1W[c * INCH + t], a);
        y[t] = fmaxf(a, 0.f);
    }
    __syncthreads();
    if (t < 2) {
        float o = l2b[t];
        for (int j = 0; j < NROI; j++) o = fmaf(y[j], l2W[j * 2 + t], o);
        out[g * 2 + t] = o;
    }
}

extern "C" void kernel_launch(void* const* d_in, const int* in_sizes, int n_in,
                              void* d_out, int out_size)
{
    const float* x    = (const float*)d_in[0];
    const float* ea   = (const float*)d_in[1];
    const float* emb  = (const float*)d_in[2];
    const float* encW = (const float*)d_in[3];
    const float* encb = (const float*)d_in[4];
    const float* bng  = (const float*)d_in[5];
    const float* bnb  = (const float*)d_in[6];
    const float* gWe  = (const float*)d_in[7];
    const float* gbe  = (const float*)d_in[8];
    const float* gW1  = (const float*)d_in[9];
    const float* gb1  = (const float*)d_in[10];
    const float* gW2  = (const float*)d_in[11];
    const float* gb2  = (const float*)d_in[12];
    const float* aWl  = (const float*)d_in[13];
    const float* abl  = (const float*)d_in[14];
    const float* aWr  = (const float*)d_in[15];
    const float* abr  = (const float*)d_in[16];
    const float* aat  = (const float*)d_in[17];
    const float* aWe  = (const float*)d_in[18];
    const float* abi  = (const float*)d_in[19];
    const float* pW1  = (const float*)d_in[20];
    const float* pb1  = (const float*)d_in[21];
    const float* pw2  = (const float*)d_in[22];
    const float* l1W  = (const float*)d_in[23];
    const float* l1b  = (const float*)d_in[24];
    const float* l2W  = (const float*)d_in[25];
    const float* l2b  = (const float*)d_in[26];
    const int*   gid  = (const int*)d_in[29];
    float* out = (float*)d_out;

    const int smEnc  = (NROI * CIN + CIN * HID + NROI * RS + HID) * 4;
    const int smGine = (2 * NROI * RS + 2 * HID * HID + EDIM * HID + ESF + 3 * HID) * 4;
    const int smGat  = (3 * NROI * RS + HID * HID + EDIM * HID + ESF + 3 * HID) * 4;
    cudaFuncSetAttribute(k_encode, cudaFuncAttributeMaxDynamicSharedMemorySize, smEnc);
    cudaFuncSetAttribute(k_gine,   cudaFuncAttributeMaxDynamicSharedMemorySize, smGine);
    cudaFuncSetAttribute(k_gat,    cudaFuncAttributeMaxDynamicSharedMemorySize, smGat);

    k_init<<<1, 64>>>();
    k_encode<<<NGR, THR, smEnc>>>(x, emb, gid, encW, encb);
    k_bnfin<<<1, 64>>>(bng, bnb);
    k_gine<<<NGR, GTHR, smGine>>>(ea, gWe, gbe, gW1, gb1, gW2, gb2);
    k_gat<<<NGR, GTHR, smGat>>>(0, ea, aWl, abl, aWr, abr, aat, aWe, abi);
    k_gat<<<NGR, GTHR, smGat>>>(1, ea, aWl, abl, aWr, abr, aat, aWe, abi);
    k_pool1<<<NGR, 512>>>(pW1, pb1, pw2);
    k_pool2<<<1, 1024>>>();
    k_pool3<<<NGR, 128>>>(l1W, l1b, l2W, l2b, out);
}